// round 11
// baseline (speedup 1.0000x reference)
#include <cuda_runtime.h>
#include <cuda_fp16.h>
#include <cstdint>

// Problem constants (hetero SAGEConv, 3 layers, 3 etypes)
#define DIM      64
#define NTYPES   3
#define NLAYERS  3
#define MAXN     100000
#define MAXE     400000
#define NSEG     (NTYPES * MAXN)
#define CHUNK    4096                 // scan chunk: 256 threads x 16 items
#define NMATS    16                   // 6+6 hidden + (wsum + 3 Wn) last
#define GEMM_GRID 296                 // 2 CTAs x 148 SMs, persistent

// Scratch: device globals (no runtime allocation allowed).
__device__ __half g_hh[2][(size_t)MAXN * DIM];          // ping-pong hidden (fp16)
__device__ __half g_aggh[(size_t)NTYPES * MAXN * DIM];  // per-etype means (fp16)
__device__ int    g_csr_src[(size_t)NTYPES * MAXE];     // src ids grouped by (etype,dst)
__device__ int    g_off[NSEG + 1];
__device__ int    g_cur[NSEG];
__device__ int    g_bsums[1024];
// Weight fragments, fp16, B-operand layout for mma.m16n8k16:
// [mat][kstep 0..3][colgroup 0..7][lane 0..31] as uint2 (two half2)
__device__ uint2  g_wfrag[(size_t)NMATS * 4 * 8 * 32];

// ---------------------------------------------------------------------------
// helpers
// ---------------------------------------------------------------------------
__device__ __forceinline__ uint32_t pack_h2(float a, float b) {
    __half2 h = __floats2half2_rn(a, b);
    return *reinterpret_cast<uint32_t*>(&h);
}

__device__ __forceinline__ void mma_f16(float d[4], const uint32_t a[4],
                                        uint32_t b0, uint32_t b1) {
    asm volatile(
        "mma.sync.aligned.m16n8k16.row.col.f32.f16.f16.f32 "
        "{%0,%1,%2,%3}, {%4,%5,%6,%7}, {%8,%9}, {%0,%1,%2,%3};\n"
        : "+f"(d[0]), "+f"(d[1]), "+f"(d[2]), "+f"(d[3])
        : "r"(a[0]), "r"(a[1]), "r"(a[2]), "r"(a[3]), "r"(b0), "r"(b1));
}

__device__ __forceinline__ void ldsm_x4(uint32_t a[4], uint32_t addr) {
    asm volatile("ldmatrix.sync.aligned.m8n8.x4.shared.b16 {%0,%1,%2,%3}, [%4];"
                 : "=r"(a[0]), "=r"(a[1]), "=r"(a[2]), "=r"(a[3]) : "r"(addr));
}

// ---------------------------------------------------------------------------
// zero int4 region
// ---------------------------------------------------------------------------
__global__ void zero_i4(int4* __restrict__ p, int n4) {
    int i = blockIdx.x * blockDim.x + threadIdx.x;
    if (i < n4) p[i] = make_int4(0, 0, 0, 0);
}

// ---------------------------------------------------------------------------
// Fused: histogram + weight prep + feat->fp16 (independent block ranges).
// ---------------------------------------------------------------------------
__global__ void hist_prep_kernel(const int* __restrict__ dst,
                                 int* __restrict__ cnt,
                                 const float* __restrict__ Ws,
                                 const float* __restrict__ Wn,
                                 const float4* __restrict__ feat4,
                                 uint2* __restrict__ hout,
                                 int E, int N, int nbH, int fn4) {
    int bx = blockIdx.x;
    if (bx < nbH) {
        int i = bx * 256 + threadIdx.x;
        if (i < NTYPES * E) {
            int t = (i >= E) + (i >= 2 * E);
            atomicAdd(&cnt[t * N + dst[i]], 1);
        }
    } else if (bx < nbH + 64) {
        int idx = (bx - nbH) * 256 + threadIdx.x;   // < 16384 = NMATS*1024
        int m    = idx >> 10;
        int r    = idx & 1023;
        int ks   = r >> 8;             // 0..3
        int cg   = (r >> 5) & 7;       // 0..7
        int lane = r & 31;
        int col  = cg * 8 + (lane >> 2);
        int kb   = ks * 16 + (lane & 3) * 2;

        float w[4];
        if (m < 12) {
            int l = m / 6, j = m % 6;
            const float* W = (j < 3) ? Ws + ((size_t)l * 3 + j) * 4096
                                     : Wn + ((size_t)l * 3 + (j - 3)) * 4096;
            w[0] = W[kb * 64 + col];       w[1] = W[(kb + 1) * 64 + col];
            w[2] = W[(kb + 8) * 64 + col]; w[3] = W[(kb + 9) * 64 + col];
        } else if (m == 12) {
            const float* W0 = Ws + (size_t)2 * 3 * 4096;
#pragma unroll
            for (int q = 0; q < 4; q++) {
                int k = kb + (q & 1) + (q >> 1) * 8;
                w[q] = W0[k * 64 + col] + W0[4096 + k * 64 + col]
                     + W0[8192 + k * 64 + col];
            }
        } else {
            const float* W = Wn + ((size_t)2 * 3 + (m - 13)) * 4096;
            w[0] = W[kb * 64 + col];       w[1] = W[(kb + 1) * 64 + col];
            w[2] = W[(kb + 8) * 64 + col]; w[3] = W[(kb + 9) * 64 + col];
        }
        g_wfrag[idx] = make_uint2(pack_h2(w[0], w[1]), pack_h2(w[2], w[3]));
    } else {
        int i = (bx - nbH - 64) * 256 + threadIdx.x;
        if (i < fn4) {
            float4 v = feat4[i];
            hout[i] = make_uint2(pack_h2(v.x, v.y), pack_h2(v.z, v.w));
        }
    }
}

// ---------------------------------------------------------------------------
// CSR scan chain: scan1 -> scan2 -> scan3
// ---------------------------------------------------------------------------
__global__ __launch_bounds__(256)
void scan1_kernel(const int* __restrict__ in, int* __restrict__ out,
                  int* __restrict__ bsums, int n) {
    __shared__ int sh[256];
    int b = blockIdx.x, t = threadIdx.x;
    int base = b * CHUNK + t * 16;
    int vals[16];
    int sum = 0;
#pragma unroll
    for (int i = 0; i < 16; i++) {
        int idx = base + i;
        int v = (idx < n) ? in[idx] : 0;
        vals[i] = sum;
        sum += v;
    }
    sh[t] = sum;
    __syncthreads();
    for (int off = 1; off < 256; off <<= 1) {
        int v = (t >= off) ? sh[t - off] : 0;
        __syncthreads();
        sh[t] += v;
        __syncthreads();
    }
    int texcl = (t == 0) ? 0 : sh[t - 1];
#pragma unroll
    for (int i = 0; i < 16; i++) {
        int idx = base + i;
        if (idx < n) out[idx] = vals[i] + texcl;
    }
    if (t == 255) bsums[b] = sh[255];
}

__global__ void scan2_kernel(int* __restrict__ bsums, int nb) {
    __shared__ int sh[128];
    int t = threadIdx.x;
    int v = (t < nb) ? bsums[t] : 0;
    sh[t] = v;
    __syncthreads();
    for (int off = 1; off < 128; off <<= 1) {
        int u = (t >= off) ? sh[t - off] : 0;
        __syncthreads();
        sh[t] += u;
        __syncthreads();
    }
    if (t < nb) bsums[t] = sh[t] - v;   // exclusive
}

__global__ void scan3_kernel(int* __restrict__ off, int* __restrict__ cur,
                             const int* __restrict__ bsums, int n, int total) {
    int i = blockIdx.x * blockDim.x + threadIdx.x;
    if (i < n) {
        int v = off[i] + bsums[i / CHUNK];
        off[i] = v;
        cur[i] = v;
    }
    if (i == 0) off[n] = total;
}

__global__ void fill_kernel(const int* __restrict__ src, const int* __restrict__ dst,
                            int* __restrict__ cur, int* __restrict__ csr,
                            int E, int N) {
    int i = blockIdx.x * blockDim.x + threadIdx.x;
    if (i < NTYPES * E) {
        int t = (i >= E) + (i >= 2 * E);
        int pos = atomicAdd(&cur[t * N + dst[i]], 1);
        csr[pos] = src[i];
    }
}

// ---------------------------------------------------------------------------
// Gather-mean aggregation (fp16 h): 8 lanes per segment, 8 dims per lane.
// Edge loop unrolled x4 (avg degree 4) for MLP-4 latency hiding.
// fp32 accumulation, fp16 output.
// ---------------------------------------------------------------------------
__global__ __launch_bounds__(256)
void agg_kernel(const __half* __restrict__ h, const int* __restrict__ off,
                const int* __restrict__ csr, __half* __restrict__ aggh, int nseg) {
    long long gid = (long long)blockIdx.x * blockDim.x + threadIdx.x;
    int seg = (int)(gid >> 3);
    if (seg >= nseg) return;
    int lane = (int)(gid & 7);
    int b = __ldg(&off[seg]);
    int e = __ldg(&off[seg + 1]);
    float acc[8] = {0.f, 0.f, 0.f, 0.f, 0.f, 0.f, 0.f, 0.f};
    if (b < e) {
        int i = b;
        for (; i + 3 < e; i += 4) {
            int s0 = __ldg(&csr[i]);
            int s1 = __ldg(&csr[i + 1]);
            int s2 = __ldg(&csr[i + 2]);
            int s3 = __ldg(&csr[i + 3]);
            uint4 v0 = *(const uint4*)(h + (size_t)s0 * DIM + lane * 8);
            uint4 v1 = *(const uint4*)(h + (size_t)s1 * DIM + lane * 8);
            uint4 v2 = *(const uint4*)(h + (size_t)s2 * DIM + lane * 8);
            uint4 v3 = *(const uint4*)(h + (size_t)s3 * DIM + lane * 8);
            const __half2* p0 = reinterpret_cast<const __half2*>(&v0);
            const __half2* p1 = reinterpret_cast<const __half2*>(&v1);
            const __half2* p2 = reinterpret_cast<const __half2*>(&v2);
            const __half2* p3 = reinterpret_cast<const __half2*>(&v3);
#pragma unroll
            for (int j = 0; j < 4; j++) {
                float2 f0 = __half22float2(p0[j]);
                float2 f1 = __half22float2(p1[j]);
                float2 f2 = __half22float2(p2[j]);
                float2 f3 = __half22float2(p3[j]);
                acc[j * 2]     += (f0.x + f1.x) + (f2.x + f3.x);
                acc[j * 2 + 1] += (f0.y + f1.y) + (f2.y + f3.y);
            }
        }
        for (; i < e; i++) {
            int s0 = __ldg(&csr[i]);
            uint4 v0 = *(const uint4*)(h + (size_t)s0 * DIM + lane * 8);
            const __half2* p0 = reinterpret_cast<const __half2*>(&v0);
#pragma unroll
            for (int j = 0; j < 4; j++) {
                float2 f0 = __half22float2(p0[j]);
                acc[j * 2]     += f0.x;
                acc[j * 2 + 1] += f0.y;
            }
        }
        float w = 1.0f / (float)(e - b);
#pragma unroll
        for (int j = 0; j < 8; j++) acc[j] *= w;
    }
    uint4 o;
    o.x = pack_h2(acc[0], acc[1]);
    o.y = pack_h2(acc[2], acc[3]);
    o.z = pack_h2(acc[4], acc[5]);
    o.w = pack_h2(acc[6], acc[7]);
    *(uint4*)(aggh + (size_t)seg * DIM + lane * 8) = o;
}

// ---------------------------------------------------------------------------
// Hidden layer, fp16 MMA (m16n8k16, fp32 accum), PERSISTENT grid-stride:
//   out[n] = sum_t relu( h[n] @ Ws_t + mean_t[n] @ Wn_t + b_t )   (fp16 out)
// 296 blocks x 256 threads; each block loops over 64-row tiles.
// ---------------------------------------------------------------------------
__global__ __launch_bounds__(256, 2)
void layer_fp16_kernel(const __half* __restrict__ h,
                       const __half* __restrict__ aggh,  // [3][N*64]
                       const float* __restrict__ bias,   // [3][64]
                       __half* __restrict__ out,
                       int N, int slot0, int ntiles) {
    __shared__ uint4 sA[4 * 64 * 8];   // [src][row][unit], unit swizzled; 32 KB

    const int tid = threadIdx.x;
    const int lane = tid & 31;
    const int warp = tid >> 5;
    const int wy = warp >> 2;      // 0..1
    const int wx = warp & 3;       // 0..3
    const int lr = lane >> 2;      // 0..7
    const int lc = lane & 3;       // 0..3

    uint32_t sbase = (uint32_t)__cvta_generic_to_shared(sA);
    const int lrow  = (lane & 7) + ((lane >> 3) & 1) * 8;  // ldmatrix row id
    const int khalf = lane >> 4;                            // 0/1: k half
    const uint2* fragbase = g_wfrag + lane;

    // bias values (constant across tiles)
    float bb[3][2];
    {
        int c0 = wx * 16 + lc * 2;   // base col for ct=0; ct=1 adds 8
#pragma unroll
        for (int t = 0; t < 3; t++) {
            bb[t][0] = __ldg(&bias[t * 64 + c0]);
            bb[t][1] = __ldg(&bias[t * 64 + c0 + 1]);
        }
    }

    for (int tile = blockIdx.x; tile < ntiles; tile += gridDim.x) {
        const int row0 = tile * 64;

        // ---- stage full A tile: 4 src x 64 rows x 8 uint4 ----
#pragma unroll
        for (int p = 0; p < 8; p++) {
            int f = p * 256 + tid;         // 0..2047
            int src = f >> 9;
            int rem = f & 511;
            int row = rem >> 3;
            int unit = rem & 7;
            int rowg = row0 + row;
            uint4 v = make_uint4(0u, 0u, 0u, 0u);
            if (rowg < N) {
                const uint4* gp = (src == 0)
                    ? (const uint4*)(h + (size_t)rowg * DIM)
                    : (const uint4*)(aggh + ((size_t)(src - 1) * N + rowg) * DIM);
                v = __ldg(&gp[unit]);
            }
            sA[(src * 64 + row) * 8 + (unit ^ (row & 7))] = v;
        }
        __syncthreads();

        float acc[3][2][2][4];
#pragma unroll
        for (int t = 0; t < 3; t++)
#pragma unroll
            for (int rt = 0; rt < 2; rt++)
#pragma unroll
                for (int ct = 0; ct < 2; ct++)
#pragma unroll
                    for (int q = 0; q < 4; q++) acc[t][rt][ct][q] = 0.f;

#pragma unroll
        for (int ks = 0; ks < 4; ks++) {
            uint2 bf[6][2];
#pragma unroll
            for (int m = 0; m < 6; m++)
#pragma unroll
                for (int ct = 0; ct < 2; ct++)
                    bf[m][ct] = __ldg(&fragbase[(((size_t)(slot0 + m) * 4 + ks) * 8
                                                 + (wx * 2 + ct)) * 32]);

#pragma unroll
            for (int srcm = 0; srcm < 4; srcm++) {
                uint32_t a[2][4];
#pragma unroll
                for (int rt = 0; rt < 2; rt++) {
                    int row = wy * 32 + rt * 16 + lrow;
                    int unit = (ks * 2 + khalf) ^ (row & 7);
                    uint32_t addr = sbase + (((srcm * 64 + row) * 8 + unit) << 4);
                    ldsm_x4(a[rt], addr);
                }
                if (srcm == 0) {
#pragma unroll
                    for (int t = 0; t < 3; t++)
#pragma unroll
                        for (int rt = 0; rt < 2; rt++)
#pragma unroll
                            for (int ct = 0; ct < 2; ct++)
                                mma_f16(acc[t][rt][ct], a[rt],
                                        bf[t][ct].x, bf[t][ct].y);
                } else {
                    int t = srcm - 1;
#pragma unroll
                    for (int rt = 0; rt < 2; rt++)
#pragma unroll
                        for (int ct = 0; ct < 2; ct++)
                            mma_f16(acc[t][rt][ct], a[rt],
                                    bf[3 + t][ct].x, bf[3 + t][ct].y);
                }
            }
        }

        // ---- epilogue ----
#pragma unroll
        for (int rt = 0; rt < 2; rt++) {
#pragma unroll
            for (int ct = 0; ct < 2; ct++) {
                int c0 = wx * 16 + ct * 8 + lc * 2;
                float ov[4] = {0.f, 0.f, 0.f, 0.f};
#pragma unroll
                for (int t = 0; t < 3; t++) {
                    ov[0] += fmaxf(acc[t][rt][ct][0] + bb[t][0], 0.f);
                    ov[1] += fmaxf(acc[t][rt][ct][1] + bb[t][1], 0.f);
                    ov[2] += fmaxf(acc[t][rt][ct][2] + bb[t][0], 0.f);
                    ov[3] += fmaxf(acc[t][rt][ct][3] + bb[t][1], 0.f);
                }
                int r0 = row0 + wy * 32 + rt * 16 + lr;
                if (r0 < N)
                    *reinterpret_cast<uint32_t*>(out + (size_t)r0 * DIM + c0) =
                        pack_h2(ov[0], ov[1]);
                if (r0 + 8 < N)
                    *reinterpret_cast<uint32_t*>(out + (size_t)(r0 + 8) * DIM + c0) =
                        pack_h2(ov[2], ov[3]);
            }
        }
        __syncthreads();   // all ldmatrix reads done before restaging
    }
}

// ---------------------------------------------------------------------------
// Last layer (no ReLU, fp32 out), PERSISTENT grid-stride. Slots 12..15.
// ---------------------------------------------------------------------------
__global__ __launch_bounds__(256, 2)
void layer_last_fp16_kernel(const __half* __restrict__ h,
                            const __half* __restrict__ aggh,
                            const float* __restrict__ bias,  // [3][64]
                            float* __restrict__ out,
                            int N, int ntiles) {
    __shared__ uint4 sA[4 * 64 * 8];

    const int tid = threadIdx.x;
    const int lane = tid & 31;
    const int warp = tid >> 5;
    const int wy = warp >> 2;
    const int wx = warp & 3;
    const int lr = lane >> 2;
    const int lc = lane & 3;

    uint32_t sbase = (uint32_t)__cvta_generic_to_shared(sA);
    const int lrow  = (lane & 7) + ((lane >> 3) & 1) * 8;
    const int khalf = lane >> 4;
    const uint2* fragbase = g_wfrag + lane;

    float bsum[2];
    {
        int c0 = wx * 16 + lc * 2;
        bsum[0] = __ldg(&bias[c0]) + __ldg(&bias[64 + c0]) + __ldg(&bias[128 + c0]);
        bsum[1] = __ldg(&bias[c0 + 1]) + __ldg(&bias[64 + c0 + 1])
                + __ldg(&bias[128 + c0 + 1]);
    }

    for (int tile = blockIdx.x; tile < ntiles; tile += gridDim.x) {
        const int row0 = tile * 64;

#pragma unroll
        for (int p = 0; p < 8; p++) {
            int f = p * 256 + tid;
            int src = f >> 9;
            int rem = f & 511;
            int row = rem >> 3;
            int unit = rem & 7;
            int rowg = row0 + row;
            uint4 v = make_uint4(0u, 0u, 0u, 0u);
            if (rowg < N) {
                const uint4* gp = (src == 0)
                    ? (const uint4*)(h + (size_t)rowg * DIM)
                    : (const uint4*)(aggh + ((size_t)(src - 1) * N + rowg) * DIM);
                v = __ldg(&gp[unit]);
            }
            sA[(src * 64 + row) * 8 + (unit ^ (row & 7))] = v;
        }
        __syncthreads();

        float acc[2][2][4];
#pragma unroll
        for (int rt = 0; rt < 2; rt++)
#pragma unroll
            for (int ct = 0; ct < 2; ct++)
#pragma unroll
                for (int q = 0; q < 4; q++) acc[rt][ct][q] = 0.f;

#pragma unroll
        for (int ks = 0; ks < 4; ks++) {
#pragma unroll
            for (int srcm = 0; srcm < 4; srcm++) {
                uint2 bf[2];
#pragma unroll
                for (int ct = 0; ct < 2; ct++)
                    bf[ct] = __ldg(&fragbase[(((size_t)(12 + srcm) * 4 + ks) * 8
                                              + (wx * 2 + ct)) * 32]);
                uint32_t a[2][4];
#pragma unroll
                for (int rt = 0; rt < 2; rt++) {
                    int row = wy * 32 + rt * 16 + lrow;
                    int unit = (ks * 2 + khalf) ^ (row & 7);
                    uint32_t addr = sbase + (((srcm * 64 + row) * 8 + unit) << 4);
                    ldsm_x4(a[rt], addr);
                }
#pragma unroll
                for (int rt = 0; rt < 2; rt++)
#pragma unroll
                    for (int ct = 0; ct < 2; ct++)
                        mma_f16(acc[rt][ct], a[rt], bf[ct].x, bf[ct].y);
            }
        }

#pragma unroll
        for (int rt = 0; rt < 2; rt++) {
#pragma unroll
            for (int ct = 0; ct < 2; ct++) {
                int c0 = wx * 16 + ct * 8 + lc * 2;
                int r0 = row0 + wy * 32 + rt * 16 + lr;
                if (r0 < N)
                    *(float2*)(out + (size_t)r0 * DIM + c0) =
                        make_float2(acc[rt][ct][0] + bsum[0],
                                    acc[rt][ct][1] + bsum[1]);
                if (r0 + 8 < N)
                    *(float2*)(out + (size_t)(r0 + 8) * DIM + c0) =
                        make_float2(acc[rt][ct][2] + bsum[0],
                                    acc[rt][ct][3] + bsum[1]);
            }
        }
        __syncthreads();
    }
}

// ---------------------------------------------------------------------------
// Launch
// ---------------------------------------------------------------------------
extern "C" void kernel_launch(void* const* d_in, const int* in_sizes, int n_in,
                              void* d_out, int out_size) {
    const float* feat    = (const float*)d_in[0];
    const float* W_self  = (const float*)d_in[1];
    const float* W_neigh = (const float*)d_in[2];
    const float* bias    = (const float*)d_in[3];
    const int*   src     = (const int*)d_in[4];
    const int*   dst     = (const int*)d_in[5];

    const int N = in_sizes[0] / DIM;       // 100000
    const int E = in_sizes[4] / NTYPES;    // 400000
    const int nseg = NTYPES * N;
    const int totE = NTYPES * E;
    float* out = (float*)d_out;

    void *phh, *pah, *pcsr, *poff, *pcur, *pbs;
    cudaGetSymbolAddress(&phh, g_hh);
    cudaGetSymbolAddress(&pah, g_aggh);
    cudaGetSymbolAddress(&pcsr, g_csr_src);
    cudaGetSymbolAddress(&poff, g_off);
    cudaGetSymbolAddress(&pcur, g_cur);
    cudaGetSymbolAddress(&pbs, g_bsums);
    __half* hbuf = (__half*)phh;
    __half* aggh = (__half*)pah;
    int* csr    = (int*)pcsr;
    int* off    = (int*)poff;
    int* cur    = (int*)pcur;
    int* bsums  = (int*)pbs;

    // ---- CSR build + weight prep + feat->fp16 (6 launches) ----
    {
        int n4 = (nseg + 3) / 4;
        zero_i4<<<(n4 + 255) / 256, 256>>>((int4*)cur, n4);

        int nbH = (totE + 255) / 256;
        int fn4 = N * DIM / 4;
        int nbF = (fn4 + 255) / 256;
        hist_prep_kernel<<<nbH + 64 + nbF, 256>>>(
            dst, cur, W_self, W_neigh, (const float4*)feat, (uint2*)hbuf,
            E, N, nbH, fn4);

        int nb = (nseg + CHUNK - 1) / CHUNK;
        scan1_kernel<<<nb, 256>>>(cur, off, bsums, nseg);
        scan2_kernel<<<1, 128>>>(bsums, nb);
        scan3_kernel<<<(nseg + 255) / 256, 256>>>(off, cur, bsums, nseg, totE);
        fill_kernel<<<(totE + 255) / 256, 256>>>(src, dst, cur, csr, E, N);
    }

    const int ntiles = (N + 63) / 64;
    const int agg_blocks = (int)(((long long)nseg * 8 + 255) / 256);

    const __half* h_cur = hbuf;                      // fp16 feat in slot 0
    for (int l = 0; l < NLAYERS; l++) {
        agg_kernel<<<agg_blocks, 256>>>(h_cur, off, csr, aggh, nseg);

        const float* bl = bias + (size_t)l * NTYPES * DIM;
        if (l < NLAYERS - 1) {
            __half* h_next = hbuf + (size_t)((l + 1) & 1) * MAXN * DIM;
            layer_fp16_kernel<<<GEMM_GRID, 256>>>(h_cur, aggh, bl, h_next, N,
                                                  l * 6, ntiles);
            h_cur = h_next;
        } else {
            layer_last_fp16_kernel<<<GEMM_GRID, 256>>>(h_cur, aggh, bl, out, N,
                                                       ntiles);
        }
    }
}

// round 12
// speedup vs baseline: 1.0157x; 1.0157x over previous
#include <cuda_runtime.h>
#include <cuda_fp16.h>
#include <cstdint>

// Problem constants (hetero SAGEConv, 3 layers, 3 etypes)
#define DIM      64
#define NTYPES   3
#define NLAYERS  3
#define MAXN     100000
#define MAXE     400000
#define NSEG     (NTYPES * MAXN)
#define CHUNK    4096                 // scan chunk: 256 threads x 16 items
#define NMATS    16                   // 6+6 hidden + (wsum + 3 Wn) last

// Scratch: device globals (no runtime allocation allowed).
__device__ __half g_hh[2][(size_t)MAXN * DIM];          // ping-pong hidden (fp16)
__device__ __half g_aggh[(size_t)NTYPES * MAXN * DIM];  // per-etype means (fp16)
__device__ int    g_csr_src[(size_t)NTYPES * MAXE];     // src ids grouped by (etype,dst)
__device__ int    g_off[NSEG + 1];
__device__ int    g_cur[NSEG];
__device__ int    g_bsums[1024];
// Weight fragments, fp16, B-operand layout for mma.m16n8k16:
// [mat][kstep 0..3][colgroup 0..7][lane 0..31] as uint2 (two half2)
__device__ uint2  g_wfrag[(size_t)NMATS * 4 * 8 * 32];

// ---------------------------------------------------------------------------
// helpers
// ---------------------------------------------------------------------------
__device__ __forceinline__ uint32_t pack_h2(float a, float b) {
    __half2 h = __floats2half2_rn(a, b);
    return *reinterpret_cast<uint32_t*>(&h);
}

__device__ __forceinline__ void mma_f16(float d[4], const uint32_t a[4],
                                        uint32_t b0, uint32_t b1) {
    asm volatile(
        "mma.sync.aligned.m16n8k16.row.col.f32.f16.f16.f32 "
        "{%0,%1,%2,%3}, {%4,%5,%6,%7}, {%8,%9}, {%0,%1,%2,%3};\n"
        : "+f"(d[0]), "+f"(d[1]), "+f"(d[2]), "+f"(d[3])
        : "r"(a[0]), "r"(a[1]), "r"(a[2]), "r"(a[3]), "r"(b0), "r"(b1));
}

__device__ __forceinline__ void ldsm_x4(uint32_t a[4], uint32_t addr) {
    asm volatile("ldmatrix.sync.aligned.m8n8.x4.shared.b16 {%0,%1,%2,%3}, [%4];"
                 : "=r"(a[0]), "=r"(a[1]), "=r"(a[2]), "=r"(a[3]) : "r"(addr));
}

// ---------------------------------------------------------------------------
// zero int4 region
// ---------------------------------------------------------------------------
__global__ void zero_i4(int4* __restrict__ p, int n4) {
    int i = blockIdx.x * blockDim.x + threadIdx.x;
    if (i < n4) p[i] = make_int4(0, 0, 0, 0);
}

// ---------------------------------------------------------------------------
// Fused: histogram + weight prep + feat->fp16 (independent block ranges).
// ---------------------------------------------------------------------------
__global__ void hist_prep_kernel(const int* __restrict__ dst,
                                 int* __restrict__ cnt,
                                 const float* __restrict__ Ws,
                                 const float* __restrict__ Wn,
                                 const float4* __restrict__ feat4,
                                 uint2* __restrict__ hout,
                                 int E, int N, int nbH, int fn4) {
    int bx = blockIdx.x;
    if (bx < nbH) {
        int i = bx * 256 + threadIdx.x;
        if (i < NTYPES * E) {
            int t = (i >= E) + (i >= 2 * E);
            atomicAdd(&cnt[t * N + dst[i]], 1);
        }
    } else if (bx < nbH + 64) {
        int idx = (bx - nbH) * 256 + threadIdx.x;   // < 16384 = NMATS*1024
        int m    = idx >> 10;
        int r    = idx & 1023;
        int ks   = r >> 8;             // 0..3
        int cg   = (r >> 5) & 7;       // 0..7
        int lane = r & 31;
        int col  = cg * 8 + (lane >> 2);
        int kb   = ks * 16 + (lane & 3) * 2;

        float w[4];
        if (m < 12) {
            int l = m / 6, j = m % 6;
            const float* W = (j < 3) ? Ws + ((size_t)l * 3 + j) * 4096
                                     : Wn + ((size_t)l * 3 + (j - 3)) * 4096;
            w[0] = W[kb * 64 + col];       w[1] = W[(kb + 1) * 64 + col];
            w[2] = W[(kb + 8) * 64 + col]; w[3] = W[(kb + 9) * 64 + col];
        } else if (m == 12) {
            const float* W0 = Ws + (size_t)2 * 3 * 4096;
#pragma unroll
            for (int q = 0; q < 4; q++) {
                int k = kb + (q & 1) + (q >> 1) * 8;
                w[q] = W0[k * 64 + col] + W0[4096 + k * 64 + col]
                     + W0[8192 + k * 64 + col];
            }
        } else {
            const float* W = Wn + ((size_t)2 * 3 + (m - 13)) * 4096;
            w[0] = W[kb * 64 + col];       w[1] = W[(kb + 1) * 64 + col];
            w[2] = W[(kb + 8) * 64 + col]; w[3] = W[(kb + 9) * 64 + col];
        }
        g_wfrag[idx] = make_uint2(pack_h2(w[0], w[1]), pack_h2(w[2], w[3]));
    } else {
        int i = (bx - nbH - 64) * 256 + threadIdx.x;
        if (i < fn4) {
            float4 v = feat4[i];
            hout[i] = make_uint2(pack_h2(v.x, v.y), pack_h2(v.z, v.w));
        }
    }
}

// ---------------------------------------------------------------------------
// CSR scan chain: scan1 -> scan2 -> scan3
// ---------------------------------------------------------------------------
__global__ __launch_bounds__(256)
void scan1_kernel(const int* __restrict__ in, int* __restrict__ out,
                  int* __restrict__ bsums, int n) {
    __shared__ int sh[256];
    int b = blockIdx.x, t = threadIdx.x;
    int base = b * CHUNK + t * 16;
    int vals[16];
    int sum = 0;
#pragma unroll
    for (int i = 0; i < 16; i++) {
        int idx = base + i;
        int v = (idx < n) ? in[idx] : 0;
        vals[i] = sum;
        sum += v;
    }
    sh[t] = sum;
    __syncthreads();
    for (int off = 1; off < 256; off <<= 1) {
        int v = (t >= off) ? sh[t - off] : 0;
        __syncthreads();
        sh[t] += v;
        __syncthreads();
    }
    int texcl = (t == 0) ? 0 : sh[t - 1];
#pragma unroll
    for (int i = 0; i < 16; i++) {
        int idx = base + i;
        if (idx < n) out[idx] = vals[i] + texcl;
    }
    if (t == 255) bsums[b] = sh[255];
}

__global__ void scan2_kernel(int* __restrict__ bsums, int nb) {
    __shared__ int sh[128];
    int t = threadIdx.x;
    int v = (t < nb) ? bsums[t] : 0;
    sh[t] = v;
    __syncthreads();
    for (int off = 1; off < 128; off <<= 1) {
        int u = (t >= off) ? sh[t - off] : 0;
        __syncthreads();
        sh[t] += u;
        __syncthreads();
    }
    if (t < nb) bsums[t] = sh[t] - v;   // exclusive
}

__global__ void scan3_kernel(int* __restrict__ off, int* __restrict__ cur,
                             const int* __restrict__ bsums, int n, int total) {
    int i = blockIdx.x * blockDim.x + threadIdx.x;
    if (i < n) {
        int v = off[i] + bsums[i / CHUNK];
        off[i] = v;
        cur[i] = v;
    }
    if (i == 0) off[n] = total;
}

__global__ void fill_kernel(const int* __restrict__ src, const int* __restrict__ dst,
                            int* __restrict__ cur, int* __restrict__ csr,
                            int E, int N) {
    int i = blockIdx.x * blockDim.x + threadIdx.x;
    if (i < NTYPES * E) {
        int t = (i >= E) + (i >= 2 * E);
        int pos = atomicAdd(&cur[t * N + dst[i]], 1);
        csr[pos] = src[i];
    }
}

// ---------------------------------------------------------------------------
// Gather-mean aggregation (fp16 h): 8 lanes per segment, 8 dims per lane.
// Edge loop unrolled x4 (avg degree 4) for MLP-4 latency hiding.
// fp32 accumulation, fp16 output.
// ---------------------------------------------------------------------------
__global__ __launch_bounds__(256)
void agg_kernel(const __half* __restrict__ h, const int* __restrict__ off,
                const int* __restrict__ csr, __half* __restrict__ aggh, int nseg) {
    long long gid = (long long)blockIdx.x * blockDim.x + threadIdx.x;
    int seg = (int)(gid >> 3);
    if (seg >= nseg) return;
    int lane = (int)(gid & 7);
    int b = __ldg(&off[seg]);
    int e = __ldg(&off[seg + 1]);
    float acc[8] = {0.f, 0.f, 0.f, 0.f, 0.f, 0.f, 0.f, 0.f};
    if (b < e) {
        int i = b;
        for (; i + 3 < e; i += 4) {
            int s0 = __ldg(&csr[i]);
            int s1 = __ldg(&csr[i + 1]);
            int s2 = __ldg(&csr[i + 2]);
            int s3 = __ldg(&csr[i + 3]);
            uint4 v0 = *(const uint4*)(h + (size_t)s0 * DIM + lane * 8);
            uint4 v1 = *(const uint4*)(h + (size_t)s1 * DIM + lane * 8);
            uint4 v2 = *(const uint4*)(h + (size_t)s2 * DIM + lane * 8);
            uint4 v3 = *(const uint4*)(h + (size_t)s3 * DIM + lane * 8);
            const __half2* p0 = reinterpret_cast<const __half2*>(&v0);
            const __half2* p1 = reinterpret_cast<const __half2*>(&v1);
            const __half2* p2 = reinterpret_cast<const __half2*>(&v2);
            const __half2* p3 = reinterpret_cast<const __half2*>(&v3);
#pragma unroll
            for (int j = 0; j < 4; j++) {
                float2 f0 = __half22float2(p0[j]);
                float2 f1 = __half22float2(p1[j]);
                float2 f2 = __half22float2(p2[j]);
                float2 f3 = __half22float2(p3[j]);
                acc[j * 2]     += (f0.x + f1.x) + (f2.x + f3.x);
                acc[j * 2 + 1] += (f0.y + f1.y) + (f2.y + f3.y);
            }
        }
        for (; i < e; i++) {
            int s0 = __ldg(&csr[i]);
            uint4 v0 = *(const uint4*)(h + (size_t)s0 * DIM + lane * 8);
            const __half2* p0 = reinterpret_cast<const __half2*>(&v0);
#pragma unroll
            for (int j = 0; j < 4; j++) {
                float2 f0 = __half22float2(p0[j]);
                acc[j * 2]     += f0.x;
                acc[j * 2 + 1] += f0.y;
            }
        }
        float w = 1.0f / (float)(e - b);
#pragma unroll
        for (int j = 0; j < 8; j++) acc[j] *= w;
    }
    uint4 o;
    o.x = pack_h2(acc[0], acc[1]);
    o.y = pack_h2(acc[2], acc[3]);
    o.z = pack_h2(acc[4], acc[5]);
    o.w = pack_h2(acc[6], acc[7]);
    *(uint4*)(aggh + (size_t)seg * DIM + lane * 8) = o;
}

// ---------------------------------------------------------------------------
// Hidden layer, fp16 MMA (m16n8k16, fp32 accum):
//   out[n] = sum_t relu( h[n] @ Ws_t + mean_t[n] @ Wn_t + b_t )   (fp16 out)
// 256 threads (8 warps, 2x4), tile 64 rows x 64 cols. Whole A tile (4 sources,
// XOR-swizzled fp16) staged once; sync-free k-loop with ldmatrix fragments.
// Independent blocks (one tile each) — R10-proven structure.
// ---------------------------------------------------------------------------
__global__ __launch_bounds__(256, 2)
void layer_fp16_kernel(const __half* __restrict__ h,
                       const __half* __restrict__ aggh,  // [3][N*64]
                       const float* __restrict__ bias,   // [3][64]
                       __half* __restrict__ out,
                       int N, int slot0) {
    __shared__ uint4 sA[4 * 64 * 8];   // [src][row][unit], unit swizzled; 32 KB

    const int tid = threadIdx.x;
    const int lane = tid & 31;
    const int warp = tid >> 5;
    const int wy = warp >> 2;      // 0..1
    const int wx = warp & 3;       // 0..3
    const int lr = lane >> 2;      // 0..7
    const int lc = lane & 3;       // 0..3
    const int row0 = blockIdx.x * 64;

    // ---- stage full A tile: 4 src x 64 rows x 8 uint4 ----
#pragma unroll
    for (int p = 0; p < 8; p++) {
        int f = p * 256 + tid;         // 0..2047
        int src = f >> 9;
        int rem = f & 511;
        int row = rem >> 3;
        int unit = rem & 7;
        int rowg = row0 + row;
        uint4 v = make_uint4(0u, 0u, 0u, 0u);
        if (rowg < N) {
            const uint4* gp = (src == 0)
                ? (const uint4*)(h + (size_t)rowg * DIM)
                : (const uint4*)(aggh + ((size_t)(src - 1) * N + rowg) * DIM);
            v = __ldg(&gp[unit]);
        }
        sA[(src * 64 + row) * 8 + (unit ^ (row & 7))] = v;
    }
    __syncthreads();

    float acc[3][2][2][4];
#pragma unroll
    for (int t = 0; t < 3; t++)
#pragma unroll
        for (int rt = 0; rt < 2; rt++)
#pragma unroll
            for (int ct = 0; ct < 2; ct++)
#pragma unroll
                for (int q = 0; q < 4; q++) acc[t][rt][ct][q] = 0.f;

    uint32_t sbase = (uint32_t)__cvta_generic_to_shared(sA);
    const int lrow  = (lane & 7) + ((lane >> 3) & 1) * 8;  // ldmatrix row id
    const int khalf = lane >> 4;                            // 0/1: k-lo/k-hi 16B unit
    const uint2* fragbase = g_wfrag + lane;

#pragma unroll
    for (int ks = 0; ks < 4; ks++) {
        // B fragments: 6 mats x 2 col-groups (LDG.64, L1-resident)
        uint2 bf[6][2];
#pragma unroll
        for (int m = 0; m < 6; m++)
#pragma unroll
            for (int ct = 0; ct < 2; ct++)
                bf[m][ct] = __ldg(&fragbase[(((size_t)(slot0 + m) * 4 + ks) * 8
                                             + (wx * 2 + ct)) * 32]);

#pragma unroll
        for (int srcm = 0; srcm < 4; srcm++) {
            uint32_t a[2][4];
#pragma unroll
            for (int rt = 0; rt < 2; rt++) {
                int row = wy * 32 + rt * 16 + lrow;
                int unit = (ks * 2 + khalf) ^ (row & 7);
                uint32_t addr = sbase + (((srcm * 64 + row) * 8 + unit) << 4);
                ldsm_x4(a[rt], addr);
            }
            if (srcm == 0) {
#pragma unroll
                for (int t = 0; t < 3; t++)
#pragma unroll
                    for (int rt = 0; rt < 2; rt++)
#pragma unroll
                        for (int ct = 0; ct < 2; ct++)
                            mma_f16(acc[t][rt][ct], a[rt], bf[t][ct].x, bf[t][ct].y);
            } else {
                int t = srcm - 1;
#pragma unroll
                for (int rt = 0; rt < 2; rt++)
#pragma unroll
                    for (int ct = 0; ct < 2; ct++)
                        mma_f16(acc[t][rt][ct], a[rt], bf[3 + t][ct].x, bf[3 + t][ct].y);
            }
        }
    }

    // ---- epilogue: bias + relu per relation, sum, fp16 store ----
#pragma unroll
    for (int rt = 0; rt < 2; rt++) {
#pragma unroll
        for (int ct = 0; ct < 2; ct++) {
            int c0 = wx * 16 + ct * 8 + lc * 2;
            float ov[4] = {0.f, 0.f, 0.f, 0.f};
#pragma unroll
            for (int t = 0; t < 3; t++) {
                float b0 = __ldg(&bias[t * 64 + c0]);
                float b1 = __ldg(&bias[t * 64 + c0 + 1]);
                ov[0] += fmaxf(acc[t][rt][ct][0] + b0, 0.f);
                ov[1] += fmaxf(acc[t][rt][ct][1] + b1, 0.f);
                ov[2] += fmaxf(acc[t][rt][ct][2] + b0, 0.f);
                ov[3] += fmaxf(acc[t][rt][ct][3] + b1, 0.f);
            }
            int r0 = row0 + wy * 32 + rt * 16 + lr;
            if (r0 < N)
                *reinterpret_cast<uint32_t*>(out + (size_t)r0 * DIM + c0) =
                    pack_h2(ov[0], ov[1]);
            if (r0 + 8 < N)
                *reinterpret_cast<uint32_t*>(out + (size_t)(r0 + 8) * DIM + c0) =
                    pack_h2(ov[2], ov[3]);
        }
    }
}

// ---------------------------------------------------------------------------
// Last layer (no ReLU, fp32 out): out = h@Wsum + sum_t mean_t@Wn_t + sum_t b_t
// Slots: 12 (wsum, pairs with h), 13..15 (Wn_t, pairs with mean_t).
// ---------------------------------------------------------------------------
__global__ __launch_bounds__(256, 2)
void layer_last_fp16_kernel(const __half* __restrict__ h,
                            const __half* __restrict__ aggh,
                            const float* __restrict__ bias,  // [3][64]
                            float* __restrict__ out,
                            int N) {
    __shared__ uint4 sA[4 * 64 * 8];

    const int tid = threadIdx.x;
    const int lane = tid & 31;
    const int warp = tid >> 5;
    const int wy = warp >> 2;
    const int wx = warp & 3;
    const int lr = lane >> 2;
    const int lc = lane & 3;
    const int row0 = blockIdx.x * 64;

#pragma unroll
    for (int p = 0; p < 8; p++) {
        int f = p * 256 + tid;
        int src = f >> 9;
        int rem = f & 511;
        int row = rem >> 3;
        int unit = rem & 7;
        int rowg = row0 + row;
        uint4 v = make_uint4(0u, 0u, 0u, 0u);
        if (rowg < N) {
            const uint4* gp = (src == 0)
                ? (const uint4*)(h + (size_t)rowg * DIM)
                : (const uint4*)(aggh + ((size_t)(src - 1) * N + rowg) * DIM);
            v = __ldg(&gp[unit]);
        }
        sA[(src * 64 + row) * 8 + (unit ^ (row & 7))] = v;
    }
    __syncthreads();

    float acc[2][2][4];
#pragma unroll
    for (int rt = 0; rt < 2; rt++)
#pragma unroll
        for (int ct = 0; ct < 2; ct++)
#pragma unroll
            for (int q = 0; q < 4; q++) acc[rt][ct][q] = 0.f;

    uint32_t sbase = (uint32_t)__cvta_generic_to_shared(sA);
    const int lrow  = (lane & 7) + ((lane >> 3) & 1) * 8;
    const int khalf = lane >> 4;
    const uint2* fragbase = g_wfrag + lane;

#pragma unroll
    for (int ks = 0; ks < 4; ks++) {
#pragma unroll
        for (int srcm = 0; srcm < 4; srcm++) {
            uint2 bf[2];
#pragma unroll
            for (int ct = 0; ct < 2; ct++)
                bf[ct] = __ldg(&fragbase[(((size_t)(12 + srcm) * 4 + ks) * 8
                                          + (wx * 2 + ct)) * 32]);
            uint32_t a[2][4];
#pragma unroll
            for (int rt = 0; rt < 2; rt++) {
                int row = wy * 32 + rt * 16 + lrow;
                int unit = (ks * 2 + khalf) ^ (row & 7);
                uint32_t addr = sbase + (((srcm * 64 + row) * 8 + unit) << 4);
                ldsm_x4(a[rt], addr);
            }
#pragma unroll
            for (int rt = 0; rt < 2; rt++)
#pragma unroll
                for (int ct = 0; ct < 2; ct++)
                    mma_f16(acc[rt][ct], a[rt], bf[ct].x, bf[ct].y);
        }
    }

#pragma unroll
    for (int rt = 0; rt < 2; rt++) {
#pragma unroll
        for (int ct = 0; ct < 2; ct++) {
            int c0 = wx * 16 + ct * 8 + lc * 2;
            float b0 = __ldg(&bias[c0])     + __ldg(&bias[64 + c0])
                     + __ldg(&bias[128 + c0]);
            float b1 = __ldg(&bias[c0 + 1]) + __ldg(&bias[64 + c0 + 1])
                     + __ldg(&bias[128 + c0 + 1]);
            int r0 = row0 + wy * 32 + rt * 16 + lr;
            if (r0 < N)
                *(float2*)(out + (size_t)r0 * DIM + c0) =
                    make_float2(acc[rt][ct][0] + b0, acc[rt][ct][1] + b1);
            if (r0 + 8 < N)
                *(float2*)(out + (size_t)(r0 + 8) * DIM + c0) =
                    make_float2(acc[rt][ct][2] + b0, acc[rt][ct][3] + b1);
        }
    }
}

// ---------------------------------------------------------------------------
// Launch
// ---------------------------------------------------------------------------
extern "C" void kernel_launch(void* const* d_in, const int* in_sizes, int n_in,
                              void* d_out, int out_size) {
    const float* feat    = (const float*)d_in[0];
    const float* W_self  = (const float*)d_in[1];
    const float* W_neigh = (const float*)d_in[2];
    const float* bias    = (const float*)d_in[3];
    const int*   src     = (const int*)d_in[4];
    const int*   dst     = (const int*)d_in[5];

    const int N = in_sizes[0] / DIM;       // 100000
    const int E = in_sizes[4] / NTYPES;    // 400000
    const int nseg = NTYPES * N;
    const int totE = NTYPES * E;
    float* out = (float*)d_out;

    void *phh, *pah, *pcsr, *poff, *pcur, *pbs;
    cudaGetSymbolAddress(&phh, g_hh);
    cudaGetSymbolAddress(&pah, g_aggh);
    cudaGetSymbolAddress(&pcsr, g_csr_src);
    cudaGetSymbolAddress(&poff, g_off);
    cudaGetSymbolAddress(&pcur, g_cur);
    cudaGetSymbolAddress(&pbs, g_bsums);
    __half* hbuf = (__half*)phh;
    __half* aggh = (__half*)pah;
    int* csr    = (int*)pcsr;
    int* off    = (int*)poff;
    int* cur    = (int*)pcur;
    int* bsums  = (int*)pbs;

    // ---- CSR build + weight prep + feat->fp16 (6 launches) ----
    {
        int n4 = (nseg + 3) / 4;
        zero_i4<<<(n4 + 255) / 256, 256>>>((int4*)cur, n4);

        int nbH = (totE + 255) / 256;
        int fn4 = N * DIM / 4;
        int nbF = (fn4 + 255) / 256;
        hist_prep_kernel<<<nbH + 64 + nbF, 256>>>(
            dst, cur, W_self, W_neigh, (const float4*)feat, (uint2*)hbuf,
            E, N, nbH, fn4);

        int nb = (nseg + CHUNK - 1) / CHUNK;
        scan1_kernel<<<nb, 256>>>(cur, off, bsums, nseg);
        scan2_kernel<<<1, 128>>>(bsums, nb);
        scan3_kernel<<<(nseg + 255) / 256, 256>>>(off, cur, bsums, nseg, totE);
        fill_kernel<<<(totE + 255) / 256, 256>>>(src, dst, cur, csr, E, N);
    }

    const int nblocks_gemm = (N + 63) / 64;
    const int agg_blocks = (int)(((long long)nseg * 8 + 255) / 256);

    const __half* h_cur = hbuf;                      // fp16 feat in slot 0
    for (int l = 0; l < NLAYERS; l++) {
        agg_kernel<<<agg_blocks, 256>>>(h_cur, off, csr, aggh, nseg);

        const float* bl = bias + (size_t)l * NTYPES * DIM;
        if (l < NLAYERS - 1) {
            __half* h_next = hbuf + (size_t)((l + 1) & 1) * MAXN * DIM;
            layer_fp16_kernel<<<nblocks_gemm, 256>>>(h_cur, aggh, bl, h_next, N, l * 6);
            h_cur = h_next;
        } else {
            layer_last_fp16_kernel<<<nblocks_gemm, 256>>>(h_cur, aggh, bl, out, N);
        }
    }
}

// round 13
// speedup vs baseline: 1.1908x; 1.1723x over previous
#include <cuda_runtime.h>
#include <cuda_fp16.h>
#include <cstdint>

// Problem constants (hetero SAGEConv, 3 layers, 3 etypes)
#define DIM      64
#define NTYPES   3
#define NLAYERS  3
#define MAXN     100000
#define MAXE     400000
#define NSEG     (NTYPES * MAXN)
#define CHUNK    4096                 // scan chunk: 256 threads x 16 items
#define NMATS    16                   // 6+6 hidden + (wsum + 3 Wn) last

// Scratch: device globals (no runtime allocation allowed).
__device__ __half g_hh[2][(size_t)MAXN * DIM];          // ping-pong hidden (fp16)
__device__ __half g_aggh[(size_t)NTYPES * MAXN * DIM];  // per-etype means (fp16)
__device__ int    g_csr_src[(size_t)NTYPES * MAXE];     // src ids grouped by (etype,dst)
__device__ int    g_off[NSEG + 1];
__device__ int    g_cur[NSEG];
__device__ int    g_bsums[1024];
// Weight fragments, fp16, B-operand layout for mma.m16n8k16:
// [mat][kstep 0..3][colgroup 0..7][lane 0..31] as uint2 (two half2)
__device__ uint2  g_wfrag[(size_t)NMATS * 4 * 8 * 32];

// ---------------------------------------------------------------------------
// helpers
// ---------------------------------------------------------------------------
__device__ __forceinline__ uint32_t pack_h2(float a, float b) {
    __half2 h = __floats2half2_rn(a, b);
    return *reinterpret_cast<uint32_t*>(&h);
}

__device__ __forceinline__ void mma_f16(float d[4], const uint32_t a[4],
                                        uint32_t b0, uint32_t b1) {
    asm volatile(
        "mma.sync.aligned.m16n8k16.row.col.f32.f16.f16.f32 "
        "{%0,%1,%2,%3}, {%4,%5,%6,%7}, {%8,%9}, {%0,%1,%2,%3};\n"
        : "+f"(d[0]), "+f"(d[1]), "+f"(d[2]), "+f"(d[3])
        : "r"(a[0]), "r"(a[1]), "r"(a[2]), "r"(a[3]), "r"(b0), "r"(b1));
}

__device__ __forceinline__ void ldsm_x4(uint32_t a[4], uint32_t addr) {
    asm volatile("ldmatrix.sync.aligned.m8n8.x4.shared.b16 {%0,%1,%2,%3}, [%4];"
                 : "=r"(a[0]), "=r"(a[1]), "=r"(a[2]), "=r"(a[3]) : "r"(addr));
}

// ---------------------------------------------------------------------------
// zero int4 region
// ---------------------------------------------------------------------------
__global__ void zero_i4(int4* __restrict__ p, int n4) {
    int i = blockIdx.x * blockDim.x + threadIdx.x;
    if (i < n4) p[i] = make_int4(0, 0, 0, 0);
}

// ---------------------------------------------------------------------------
// Fused: histogram + weight prep + feat->fp16 (independent block ranges).
// ---------------------------------------------------------------------------
__global__ void hist_prep_kernel(const int* __restrict__ dst,
                                 int* __restrict__ cnt,
                                 const float* __restrict__ Ws,
                                 const float* __restrict__ Wn,
                                 const float4* __restrict__ feat4,
                                 uint2* __restrict__ hout,
                                 int E, int N, int nbH, int fn4) {
    int bx = blockIdx.x;
    if (bx < nbH) {
        int i = bx * 256 + threadIdx.x;
        if (i < NTYPES * E) {
            int t = (i >= E) + (i >= 2 * E);
            atomicAdd(&cnt[t * N + dst[i]], 1);
        }
    } else if (bx < nbH + 64) {
        int idx = (bx - nbH) * 256 + threadIdx.x;   // < 16384 = NMATS*1024
        int m    = idx >> 10;
        int r    = idx & 1023;
        int ks   = r >> 8;             // 0..3
        int cg   = (r >> 5) & 7;       // 0..7
        int lane = r & 31;
        int col  = cg * 8 + (lane >> 2);
        int kb   = ks * 16 + (lane & 3) * 2;

        float w[4];
        if (m < 12) {
            int l = m / 6, j = m % 6;
            const float* W = (j < 3) ? Ws + ((size_t)l * 3 + j) * 4096
                                     : Wn + ((size_t)l * 3 + (j - 3)) * 4096;
            w[0] = W[kb * 64 + col];       w[1] = W[(kb + 1) * 64 + col];
            w[2] = W[(kb + 8) * 64 + col]; w[3] = W[(kb + 9) * 64 + col];
        } else if (m == 12) {
            const float* W0 = Ws + (size_t)2 * 3 * 4096;
#pragma unroll
            for (int q = 0; q < 4; q++) {
                int k = kb + (q & 1) + (q >> 1) * 8;
                w[q] = W0[k * 64 + col] + W0[4096 + k * 64 + col]
                     + W0[8192 + k * 64 + col];
            }
        } else {
            const float* W = Wn + ((size_t)2 * 3 + (m - 13)) * 4096;
            w[0] = W[kb * 64 + col];       w[1] = W[(kb + 1) * 64 + col];
            w[2] = W[(kb + 8) * 64 + col]; w[3] = W[(kb + 9) * 64 + col];
        }
        g_wfrag[idx] = make_uint2(pack_h2(w[0], w[1]), pack_h2(w[2], w[3]));
    } else {
        int i = (bx - nbH - 64) * 256 + threadIdx.x;
        if (i < fn4) {
            float4 v = feat4[i];
            hout[i] = make_uint2(pack_h2(v.x, v.y), pack_h2(v.z, v.w));
        }
    }
}

// ---------------------------------------------------------------------------
// CSR scan chain: scan1 -> scan2 -> scan3
// ---------------------------------------------------------------------------
__global__ __launch_bounds__(256)
void scan1_kernel(const int* __restrict__ in, int* __restrict__ out,
                  int* __restrict__ bsums, int n) {
    __shared__ int sh[256];
    int b = blockIdx.x, t = threadIdx.x;
    int base = b * CHUNK + t * 16;
    int vals[16];
    int sum = 0;
#pragma unroll
    for (int i = 0; i < 16; i++) {
        int idx = base + i;
        int v = (idx < n) ? in[idx] : 0;
        vals[i] = sum;
        sum += v;
    }
    sh[t] = sum;
    __syncthreads();
    for (int off = 1; off < 256; off <<= 1) {
        int v = (t >= off) ? sh[t - off] : 0;
        __syncthreads();
        sh[t] += v;
        __syncthreads();
    }
    int texcl = (t == 0) ? 0 : sh[t - 1];
#pragma unroll
    for (int i = 0; i < 16; i++) {
        int idx = base + i;
        if (idx < n) out[idx] = vals[i] + texcl;
    }
    if (t == 255) bsums[b] = sh[255];
}

__global__ void scan2_kernel(int* __restrict__ bsums, int nb) {
    __shared__ int sh[128];
    int t = threadIdx.x;
    int v = (t < nb) ? bsums[t] : 0;
    sh[t] = v;
    __syncthreads();
    for (int off = 1; off < 128; off <<= 1) {
        int u = (t >= off) ? sh[t - off] : 0;
        __syncthreads();
        sh[t] += u;
        __syncthreads();
    }
    if (t < nb) bsums[t] = sh[t] - v;   // exclusive
}

__global__ void scan3_kernel(int* __restrict__ off, int* __restrict__ cur,
                             const int* __restrict__ bsums, int n, int total) {
    int i = blockIdx.x * blockDim.x + threadIdx.x;
    if (i < n) {
        int v = off[i] + bsums[i / CHUNK];
        off[i] = v;
        cur[i] = v;
    }
    if (i == 0) off[n] = total;
}

__global__ void fill_kernel(const int* __restrict__ src, const int* __restrict__ dst,
                            int* __restrict__ cur, int* __restrict__ csr,
                            int E, int N) {
    int i = blockIdx.x * blockDim.x + threadIdx.x;
    if (i < NTYPES * E) {
        int t = (i >= E) + (i >= 2 * E);
        int pos = atomicAdd(&cur[t * N + dst[i]], 1);
        csr[pos] = src[i];
    }
}

// ---------------------------------------------------------------------------
// Gather-mean aggregation (fp16 h): 8 lanes per segment, 8 dims per lane.
// Edge loop unrolled x2 so two h-row loads are in flight per iteration.
// fp32 accumulation, fp16 output.
// ---------------------------------------------------------------------------
__global__ __launch_bounds__(256)
void agg_kernel(const __half* __restrict__ h, const int* __restrict__ off,
                const int* __restrict__ csr, __half* __restrict__ aggh, int nseg) {
    long long gid = (long long)blockIdx.x * blockDim.x + threadIdx.x;
    int seg = (int)(gid >> 3);
    if (seg >= nseg) return;
    int lane = (int)(gid & 7);
    int b = __ldg(&off[seg]);
    int e = __ldg(&off[seg + 1]);
    float acc[8] = {0.f, 0.f, 0.f, 0.f, 0.f, 0.f, 0.f, 0.f};
    if (b < e) {
        int i = b;
        for (; i + 1 < e; i += 2) {
            int s0 = __ldg(&csr[i]);
            int s1 = __ldg(&csr[i + 1]);
            uint4 v0 = *(const uint4*)(h + (size_t)s0 * DIM + lane * 8);
            uint4 v1 = *(const uint4*)(h + (size_t)s1 * DIM + lane * 8);
            const __half2* p0 = reinterpret_cast<const __half2*>(&v0);
            const __half2* p1 = reinterpret_cast<const __half2*>(&v1);
#pragma unroll
            for (int j = 0; j < 4; j++) {
                float2 f0 = __half22float2(p0[j]);
                float2 f1 = __half22float2(p1[j]);
                acc[j * 2]     += f0.x + f1.x;
                acc[j * 2 + 1] += f0.y + f1.y;
            }
        }
        if (i < e) {
            int s0 = __ldg(&csr[i]);
            uint4 v0 = *(const uint4*)(h + (size_t)s0 * DIM + lane * 8);
            const __half2* p0 = reinterpret_cast<const __half2*>(&v0);
#pragma unroll
            for (int j = 0; j < 4; j++) {
                float2 f0 = __half22float2(p0[j]);
                acc[j * 2]     += f0.x;
                acc[j * 2 + 1] += f0.y;
            }
        }
        float w = 1.0f / (float)(e - b);
#pragma unroll
        for (int j = 0; j < 8; j++) acc[j] *= w;
    }
    uint4 o;
    o.x = pack_h2(acc[0], acc[1]);
    o.y = pack_h2(acc[2], acc[3]);
    o.z = pack_h2(acc[4], acc[5]);
    o.w = pack_h2(acc[6], acc[7]);
    *(uint4*)(aggh + (size_t)seg * DIM + lane * 8) = o;
}

// ---------------------------------------------------------------------------
// Hidden layer, fp16 MMA (m16n8k16, fp32 accum):
//   out[n] = sum_t relu( h[n] @ Ws_t + mean_t[n] @ Wn_t + b_t )   (fp16 out)
// 256 threads (8 warps, 2x4), tile 64 rows x 64 cols. Whole A tile (4 sources,
// XOR-swizzled fp16) staged once; sync-free k-loop with ldmatrix fragments.
// ---------------------------------------------------------------------------
__global__ __launch_bounds__(256, 2)
void layer_fp16_kernel(const __half* __restrict__ h,
                       const __half* __restrict__ aggh,  // [3][N*64]
                       const float* __restrict__ bias,   // [3][64]
                       __half* __restrict__ out,
                       int N, int slot0) {
    __shared__ uint4 sA[4 * 64 * 8];   // [src][row][unit], unit swizzled; 32 KB

    const int tid = threadIdx.x;
    const int lane = tid & 31;
    const int warp = tid >> 5;
    const int wy = warp >> 2;      // 0..1
    const int wx = warp & 3;       // 0..3
    const int lr = lane >> 2;      // 0..7
    const int lc = lane & 3;       // 0..3
    const int row0 = blockIdx.x * 64;

    // ---- stage full A tile: 4 src x 64 rows x 8 uint4 ----
#pragma unroll
    for (int p = 0; p < 8; p++) {
        int f = p * 256 + tid;         // 0..2047
        int src = f >> 9;
        int rem = f & 511;
        int row = rem >> 3;
        int unit = rem & 7;
        int rowg = row0 + row;
        uint4 v = make_uint4(0u, 0u, 0u, 0u);
        if (rowg < N) {
            const uint4* gp = (src == 0)
                ? (const uint4*)(h + (size_t)rowg * DIM)
                : (const uint4*)(aggh + ((size_t)(src - 1) * N + rowg) * DIM);
            v = __ldg(&gp[unit]);
        }
        sA[(src * 64 + row) * 8 + (unit ^ (row & 7))] = v;
    }
    __syncthreads();

    float acc[3][2][2][4];
#pragma unroll
    for (int t = 0; t < 3; t++)
#pragma unroll
        for (int rt = 0; rt < 2; rt++)
#pragma unroll
            for (int ct = 0; ct < 2; ct++)
#pragma unroll
                for (int q = 0; q < 4; q++) acc[t][rt][ct][q] = 0.f;

    uint32_t sbase = (uint32_t)__cvta_generic_to_shared(sA);
    const int lrow  = (lane & 7) + ((lane >> 3) & 1) * 8;  // ldmatrix row id
    const int khalf = lane >> 4;                            // 0/1: k-lo/k-hi 16B unit
    const uint2* fragbase = g_wfrag + lane;

#pragma unroll
    for (int ks = 0; ks < 4; ks++) {
        // B fragments: 6 mats x 2 col-groups (LDG.64, L1-resident)
        uint2 bf[6][2];
#pragma unroll
        for (int m = 0; m < 6; m++)
#pragma unroll
            for (int ct = 0; ct < 2; ct++)
                bf[m][ct] = __ldg(&fragbase[(((size_t)(slot0 + m) * 4 + ks) * 8
                                             + (wx * 2 + ct)) * 32]);

#pragma unroll
        for (int srcm = 0; srcm < 4; srcm++) {
            uint32_t a[2][4];
#pragma unroll
            for (int rt = 0; rt < 2; rt++) {
                int row = wy * 32 + rt * 16 + lrow;
                int unit = (ks * 2 + khalf) ^ (row & 7);
                uint32_t addr = sbase + (((srcm * 64 + row) * 8 + unit) << 4);
                ldsm_x4(a[rt], addr);
            }
            if (srcm == 0) {
#pragma unroll
                for (int t = 0; t < 3; t++)
#pragma unroll
                    for (int rt = 0; rt < 2; rt++)
#pragma unroll
                        for (int ct = 0; ct < 2; ct++)
                            mma_f16(acc[t][rt][ct], a[rt], bf[t][ct].x, bf[t][ct].y);
            } else {
                int t = srcm - 1;
#pragma unroll
                for (int rt = 0; rt < 2; rt++)
#pragma unroll
                    for (int ct = 0; ct < 2; ct++)
                        mma_f16(acc[t][rt][ct], a[rt], bf[3 + t][ct].x, bf[3 + t][ct].y);
            }
        }
    }

    // ---- epilogue: bias + relu per relation, sum, fp16 store ----
#pragma unroll
    for (int rt = 0; rt < 2; rt++) {
#pragma unroll
        for (int ct = 0; ct < 2; ct++) {
            int c0 = wx * 16 + ct * 8 + lc * 2;
            float ov[4] = {0.f, 0.f, 0.f, 0.f};
#pragma unroll
            for (int t = 0; t < 3; t++) {
                float b0 = __ldg(&bias[t * 64 + c0]);
                float b1 = __ldg(&bias[t * 64 + c0 + 1]);
                ov[0] += fmaxf(acc[t][rt][ct][0] + b0, 0.f);
                ov[1] += fmaxf(acc[t][rt][ct][1] + b1, 0.f);
                ov[2] += fmaxf(acc[t][rt][ct][2] + b0, 0.f);
                ov[3] += fmaxf(acc[t][rt][ct][3] + b1, 0.f);
            }
            int r0 = row0 + wy * 32 + rt * 16 + lr;
            if (r0 < N)
                *reinterpret_cast<uint32_t*>(out + (size_t)r0 * DIM + c0) =
                    pack_h2(ov[0], ov[1]);
            if (r0 + 8 < N)
                *reinterpret_cast<uint32_t*>(out + (size_t)(r0 + 8) * DIM + c0) =
                    pack_h2(ov[2], ov[3]);
        }
    }
}

// ---------------------------------------------------------------------------
// Last layer (no ReLU, fp32 out): out = h@Wsum + sum_t mean_t@Wn_t + sum_t b_t
// Slots: 12 (wsum, pairs with h), 13..15 (Wn_t, pairs with mean_t).
// ---------------------------------------------------------------------------
__global__ __launch_bounds__(256, 2)
void layer_last_fp16_kernel(const __half* __restrict__ h,
                            const __half* __restrict__ aggh,
                            const float* __restrict__ bias,  // [3][64]
                            float* __restrict__ out,
                            int N) {
    __shared__ uint4 sA[4 * 64 * 8];

    const int tid = threadIdx.x;
    const int lane = tid & 31;
    const int warp = tid >> 5;
    const int wy = warp >> 2;
    const int wx = warp & 3;
    const int lr = lane >> 2;
    const int lc = lane & 3;
    const int row0 = blockIdx.x * 64;

#pragma unroll
    for (int p = 0; p < 8; p++) {
        int f = p * 256 + tid;
        int src = f >> 9;
        int rem = f & 511;
        int row = rem >> 3;
        int unit = rem & 7;
        int rowg = row0 + row;
        uint4 v = make_uint4(0u, 0u, 0u, 0u);
        if (rowg < N) {
            const uint4* gp = (src == 0)
                ? (const uint4*)(h + (size_t)rowg * DIM)
                : (const uint4*)(aggh + ((size_t)(src - 1) * N + rowg) * DIM);
            v = __ldg(&gp[unit]);
        }
        sA[(src * 64 + row) * 8 + (unit ^ (row & 7))] = v;
    }
    __syncthreads();

    float acc[2][2][4];
#pragma unroll
    for (int rt = 0; rt < 2; rt++)
#pragma unroll
        for (int ct = 0; ct < 2; ct++)
#pragma unroll
            for (int q = 0; q < 4; q++) acc[rt][ct][q] = 0.f;

    uint32_t sbase = (uint32_t)__cvta_generic_to_shared(sA);
    const int lrow  = (lane & 7) + ((lane >> 3) & 1) * 8;
    const int khalf = lane >> 4;
    const uint2* fragbase = g_wfrag + lane;

#pragma unroll
    for (int ks = 0; ks < 4; ks++) {
#pragma unroll
        for (int srcm = 0; srcm < 4; srcm++) {
            uint2 bf[2];
#pragma unroll
            for (int ct = 0; ct < 2; ct++)
                bf[ct] = __ldg(&fragbase[(((size_t)(12 + srcm) * 4 + ks) * 8
                                          + (wx * 2 + ct)) * 32]);
            uint32_t a[2][4];
#pragma unroll
            for (int rt = 0; rt < 2; rt++) {
                int row = wy * 32 + rt * 16 + lrow;
                int unit = (ks * 2 + khalf) ^ (row & 7);
                uint32_t addr = sbase + (((srcm * 64 + row) * 8 + unit) << 4);
                ldsm_x4(a[rt], addr);
            }
#pragma unroll
            for (int rt = 0; rt < 2; rt++)
#pragma unroll
                for (int ct = 0; ct < 2; ct++)
                    mma_f16(acc[rt][ct], a[rt], bf[ct].x, bf[ct].y);
        }
    }

#pragma unroll
    for (int rt = 0; rt < 2; rt++) {
#pragma unroll
        for (int ct = 0; ct < 2; ct++) {
            int c0 = wx * 16 + ct * 8 + lc * 2;
            float b0 = __ldg(&bias[c0])     + __ldg(&bias[64 + c0])
                     + __ldg(&bias[128 + c0]);
            float b1 = __ldg(&bias[c0 + 1]) + __ldg(&bias[64 + c0 + 1])
                     + __ldg(&bias[128 + c0 + 1]);
            int r0 = row0 + wy * 32 + rt * 16 + lr;
            if (r0 < N)
                *(float2*)(out + (size_t)r0 * DIM + c0) =
                    make_float2(acc[rt][ct][0] + b0, acc[rt][ct][1] + b1);
            if (r0 + 8 < N)
                *(float2*)(out + (size_t)(r0 + 8) * DIM + c0) =
                    make_float2(acc[rt][ct][2] + b0, acc[rt][ct][3] + b1);
        }
    }
}

// ---------------------------------------------------------------------------
// Launch
// ---------------------------------------------------------------------------
extern "C" void kernel_launch(void* const* d_in, const int* in_sizes, int n_in,
                              void* d_out, int out_size) {
    const float* feat    = (const float*)d_in[0];
    const float* W_self  = (const float*)d_in[1];
    const float* W_neigh = (const float*)d_in[2];
    const float* bias    = (const float*)d_in[3];
    const int*   src     = (const int*)d_in[4];
    const int*   dst     = (const int*)d_in[5];

    const int N = in_sizes[0] / DIM;       // 100000
    const int E = in_sizes[4] / NTYPES;    // 400000
    const int nseg = NTYPES * N;
    const int totE = NTYPES * E;
    float* out = (float*)d_out;

    void *phh, *pah, *pcsr, *poff, *pcur, *pbs;
    cudaGetSymbolAddress(&phh, g_hh);
    cudaGetSymbolAddress(&pah, g_aggh);
    cudaGetSymbolAddress(&pcsr, g_csr_src);
    cudaGetSymbolAddress(&poff, g_off);
    cudaGetSymbolAddress(&pcur, g_cur);
    cudaGetSymbolAddress(&pbs, g_bsums);
    __half* hbuf = (__half*)phh;
    __half* aggh = (__half*)pah;
    int* csr    = (int*)pcsr;
    int* off    = (int*)poff;
    int* cur    = (int*)pcur;
    int* bsums  = (int*)pbs;

    // ---- CSR build + weight prep + feat->fp16 (6 launches) ----
    {
        int n4 = (nseg + 3) / 4;
        zero_i4<<<(n4 + 255) / 256, 256>>>((int4*)cur, n4);

        int nbH = (totE + 255) / 256;
        int fn4 = N * DIM / 4;
        int nbF = (fn4 + 255) / 256;
        hist_prep_kernel<<<nbH + 64 + nbF, 256>>>(
            dst, cur, W_self, W_neigh, (const float4*)feat, (uint2*)hbuf,
            E, N, nbH, fn4);

        int nb = (nseg + CHUNK - 1) / CHUNK;
        scan1_kernel<<<nb, 256>>>(cur, off, bsums, nseg);
        scan2_kernel<<<1, 128>>>(bsums, nb);
        scan3_kernel<<<(nseg + 255) / 256, 256>>>(off, cur, bsums, nseg, totE);
        fill_kernel<<<(totE + 255) / 256, 256>>>(src, dst, cur, csr, E, N);
    }

    const int nblocks_gemm = (N + 63) / 64;
    const int agg_blocks = (int)(((long long)nseg * 8 + 255) / 256);

    const __half* h_cur = hbuf;                      // fp16 feat in slot 0
    for (int l = 0; l < NLAYERS; l++) {
        agg_kernel<<<agg_blocks, 256>>>(h_cur, off, csr, aggh, nseg);

        const float* bl = bias + (size_t)l * NTYPES * DIM;
        if (l < NLAYERS - 1) {
            __half* h_next = hbuf + (size_t)((l + 1) & 1) * MAXN * DIM;
            layer_fp16_kernel<<<nblocks_gemm, 256>>>(h_cur, aggh, bl, h_next, N, l * 6);
            h_cur = h_next;
        } else {
            layer_last_fp16_kernel<<<nblocks_gemm, 256>>>(h_cur, aggh, bl, out, N);
        }
    }
}